// round 9
// baseline (speedup 1.0000x reference)
#include <cuda_runtime.h>
#include <cstddef>

#define NB      65536
#define SEQL    5
#define HID     100
#define THREADS 512
#define WARPS   16

// Scratch for sub_mem between the two kernels (131 MB, static device array).
__device__ float g_submem[(size_t)NB * SEQL * HID];

// ---------------------------------------------------------------------------
// Packed fp32x2 FMA (sm_103a FFMA2), 128-bit shared loads, 128-bit global
// broadcast loads via __ldg (L1-cached, read-only path).
// ---------------------------------------------------------------------------
__device__ __forceinline__ void fma2(unsigned long long& acc,
                                     unsigned long long a,
                                     unsigned long long b) {
    asm volatile("fma.rn.f32x2 %0, %1, %2, %0;" : "+l"(acc) : "l"(a), "l"(b));
}
__device__ __forceinline__ void mul2(unsigned long long& d,
                                     unsigned long long a,
                                     unsigned long long b) {
    asm("mul.rn.f32x2 %0, %1, %2;" : "=l"(d) : "l"(a), "l"(b));
}
__device__ __forceinline__ void lds2(unsigned long long& a,
                                     unsigned long long& b,
                                     unsigned addr) {
    asm volatile("ld.shared.v2.u64 {%0, %1}, [%2];"
                 : "=l"(a), "=l"(b) : "r"(addr));
}
__device__ __forceinline__ void ldg2(unsigned long long& a,
                                     unsigned long long& b,
                                     const float* p) {
    float4 v = __ldg((const float4*)p);
    asm("mov.b64 %0, {%1, %2};" : "=l"(a) : "f"(v.x), "f"(v.y));
    asm("mov.b64 %0, {%1, %2};" : "=l"(b) : "f"(v.z), "f"(v.w));
}
__device__ __forceinline__ float2 unpack2(unsigned long long v) {
    float2 r;
    asm("mov.b64 {%0, %1}, %2;" : "=f"(r.x), "=f"(r.y) : "l"(v));
    return r;
}
__device__ __forceinline__ float tanh_fast(float x) {
    float e = __expf(2.0f * x);
    return 1.0f - __fdividef(2.0f, 1.0f + e);
}
__device__ __forceinline__ float sigmoid_fast(float x) {
    return __fdividef(1.0f, 1.0f + __expf(-x));
}

// ---------------------------------------------------------------------------
// Kernel 1: mem_4att / sub_4att (tanh), attention, masked softmax, sub_mem
// Shared memory holds ONLY weights + biases (x comes via LDG broadcast):
//   [0,10000)       W_mem^T  100 rows x stride 100  (40.0 KB)
//   [10000,30400)   W_sub^T  100 rows x stride 204  (81.6 KB)
//   [30400,30504)   b_mem    [30504,30608) b_sub
// Total 30,608 floats = 119.6 KiB. 16 warps/SM (register-limited).
// ---------------------------------------------------------------------------
#define K1_WTM   0
#define K1_WTS   10000
#define K1_BM    30400
#define K1_BS    30504
#define K1_SMEM_FLOATS 30608

__global__ void __launch_bounds__(THREADS, 1)
k1_attention(const float* __restrict__ sub_emb,
             const float* __restrict__ memory,
             const int*   __restrict__ sub_len,
             const float* __restrict__ sub_raw,
             const float* __restrict__ W_mem,
             const float* __restrict__ b_mem,
             const float* __restrict__ W_sub,
             const float* __restrict__ b_sub)
{
    extern __shared__ float smem[];
    const int tid = threadIdx.x;

    for (int idx = tid; idx < 100 * 100; idx += THREADS) {
        int k = idx / 100, j = idx - k * 100;
        smem[K1_WTM + j * 100 + k] = W_mem[idx];
    }
    for (int idx = tid; idx < 200 * 100; idx += THREADS) {
        int k = idx / 100, j = idx - k * 100;
        smem[K1_WTS + j * 204 + k] = W_sub[idx];
    }
    for (int idx = tid; idx < 100; idx += THREADS) {
        smem[K1_BM + idx] = b_mem[idx];
        smem[K1_BS + idx] = b_sub[idx];
    }
    __syncthreads();

    const int warp = tid >> 5, lane = tid & 31;
    const unsigned sbase = (unsigned)__cvta_generic_to_shared(smem);

    unsigned wm_addr[4], ws_addr[4];
    int jcl[4];
#pragma unroll
    for (int t = 0; t < 4; ++t) {
        int j = lane + 32 * t;
        jcl[t] = (j < 100) ? j : 99;           // clamp: garbage rows, never stored
        wm_addr[t] = sbase + (unsigned)(K1_WTM + jcl[t] * 100) * 4u;
        ws_addr[t] = sbase + (unsigned)(K1_WTS + jcl[t] * 204) * 4u;
    }

    const int gw = blockIdx.x * WARPS + warp;
    const int nw = gridDim.x * WARPS;

    for (int b = gw; b < NB; b += nw) {
        const float* mrow = memory  + (size_t)b * 500;
        const float* srow = sub_emb + (size_t)b * 500;
        const float* rrow = sub_raw + (size_t)b * 500;
        const int slen = __ldg(sub_len + b);

        // ---- mem_4att = tanh(memory @ W_mem + b_mem) ----
        unsigned long long acc[5][4];
#pragma unroll
        for (int r = 0; r < 5; ++r)
#pragma unroll
            for (int t = 0; t < 4; ++t) acc[r][t] = 0ULL;

#pragma unroll 2
        for (int k = 0; k < 100; k += 4) {
            unsigned long long w0[4], w1[4];
#pragma unroll
            for (int t = 0; t < 4; ++t) lds2(w0[t], w1[t], wm_addr[t] + k * 4);
#pragma unroll
            for (int r = 0; r < 5; ++r) {
                unsigned long long a0, a1;
                ldg2(a0, a1, mrow + r * 100 + k);
#pragma unroll
                for (int t = 0; t < 4; ++t) {
                    fma2(acc[r][t], a0, w0[t]);
                    fma2(acc[r][t], a1, w1[t]);
                }
            }
        }
        float vm[5][4];
#pragma unroll
        for (int r = 0; r < 5; ++r)
#pragma unroll
            for (int t = 0; t < 4; ++t) {
                float2 p = unpack2(acc[r][t]);
                vm[r][t] = tanh_fast(p.x + p.y + smem[K1_BM + jcl[t]]);
            }

        // ---- sub_4att = tanh(cat(sub_emb, raw) @ W_sub + b_sub) ----
#pragma unroll
        for (int r = 0; r < 5; ++r)
#pragma unroll
            for (int t = 0; t < 4; ++t) acc[r][t] = 0ULL;

        // part A: sub_emb @ W_sub[:, 0:100)
#pragma unroll 2
        for (int k = 0; k < 100; k += 4) {
            unsigned long long w0[4], w1[4];
#pragma unroll
            for (int t = 0; t < 4; ++t) lds2(w0[t], w1[t], ws_addr[t] + k * 4);
#pragma unroll
            for (int r = 0; r < 5; ++r) {
                unsigned long long a0, a1;
                ldg2(a0, a1, srow + r * 100 + k);
#pragma unroll
                for (int t = 0; t < 4; ++t) {
                    fma2(acc[r][t], a0, w0[t]);
                    fma2(acc[r][t], a1, w1[t]);
                }
            }
        }
        // part B: sub_raw @ W_sub[:, 100:200)
#pragma unroll 2
        for (int k = 0; k < 100; k += 4) {
            unsigned long long w0[4], w1[4];
#pragma unroll
            for (int t = 0; t < 4; ++t) lds2(w0[t], w1[t], ws_addr[t] + 400 + k * 4);
#pragma unroll
            for (int r = 0; r < 5; ++r) {
                unsigned long long a0, a1;
                ldg2(a0, a1, rrow + r * 100 + k);
#pragma unroll
                for (int t = 0; t < 4; ++t) {
                    fma2(acc[r][t], a0, w0[t]);
                    fma2(acc[r][t], a1, w1[t]);
                }
            }
        }
        float vs[5][4];
#pragma unroll
        for (int r = 0; r < 5; ++r)
#pragma unroll
            for (int t = 0; t < 4; ++t) {
                float2 p = unpack2(acc[r][t]);
                vs[r][t] = tanh_fast(p.x + p.y + smem[K1_BS + jcl[t]]);
            }

        // zero out clamped lanes so attention dot products are exact
#pragma unroll
        for (int r = 0; r < 5; ++r) {
            if (lane + 96 >= 100) { vm[r][3] = 0.f; vs[r][3] = 0.f; }
        }

        // ---- attention scores att[q][k'] = <sub4[q], mem4[k']> over H ----
        float att[5][5];
#pragma unroll
        for (int q = 0; q < 5; ++q)
#pragma unroll
            for (int kk = 0; kk < 5; ++kk) {
                float p = vs[q][0] * vm[kk][0];
                p = fmaf(vs[q][1], vm[kk][1], p);
                p = fmaf(vs[q][2], vm[kk][2], p);
                p = fmaf(vs[q][3], vm[kk][3], p);
                p += __shfl_xor_sync(0xffffffffu, p, 16);
                p += __shfl_xor_sync(0xffffffffu, p, 8);
                p += __shfl_xor_sync(0xffffffffu, p, 4);
                p += __shfl_xor_sync(0xffffffffu, p, 2);
                p += __shfl_xor_sync(0xffffffffu, p, 1);
                att[q][kk] = p;
            }

        // ---- masked softmax (per-query-row mask; keys never masked) ----
        float wgt[5][5];
#pragma unroll
        for (int q = 0; q < 5; ++q) {
            if (q < slen) {
                float m = att[q][0];
#pragma unroll
                for (int kk = 1; kk < 5; ++kk) m = fmaxf(m, att[q][kk]);
                float e[5], s = 0.f;
#pragma unroll
                for (int kk = 0; kk < 5; ++kk) { e[kk] = __expf(att[q][kk] - m); s += e[kk]; }
                float inv = __fdividef(1.f, s);
#pragma unroll
                for (int kk = 0; kk < 5; ++kk) wgt[q][kk] = e[kk] * inv;
            } else {
#pragma unroll
                for (int kk = 0; kk < 5; ++kk) wgt[q][kk] = 0.f;
            }
        }

        // ---- sub_mem[q] = att[q] @ memory (rows are L1-hot) ----
        float mv[5][4];
#pragma unroll
        for (int kk = 0; kk < 5; ++kk)
#pragma unroll
            for (int t = 0; t < 4; ++t) {
                int j = lane + 32 * t;
                mv[kk][t] = (j < 100) ? __ldg(mrow + kk * 100 + j) : 0.f;
            }
        float* orow = g_submem + (size_t)b * 500;
#pragma unroll
        for (int q = 0; q < 5; ++q) {
            float sm0 = 0.f, sm1 = 0.f, sm2 = 0.f, sm3 = 0.f;
#pragma unroll
            for (int kk = 0; kk < 5; ++kk) {
                sm0 = fmaf(wgt[q][kk], mv[kk][0], sm0);
                sm1 = fmaf(wgt[q][kk], mv[kk][1], sm1);
                sm2 = fmaf(wgt[q][kk], mv[kk][2], sm2);
                sm3 = fmaf(wgt[q][kk], mv[kk][3], sm3);
            }
            orow[q * 100 + lane]      = sm0;
            orow[q * 100 + lane + 32] = sm1;
            orow[q * 100 + lane + 64] = sm2;
            if (lane < 4) orow[q * 100 + lane + 96] = sm3;
        }
    }
}

// ---------------------------------------------------------------------------
// Kernel 2: g = sigmoid([sub_emb, sub_mem, sub_mem*sub_emb] @ W_gate + b);
//           out = (1-g)*sub_emb + g*sub_mem
// Shared: W_gate^T 100 rows x stride 300 (120 KB) + b_gate.
// x ranges: [0,100) se (LDG), [100,200) sub_mem (LDG), [200,300) se*sm
// computed on the fly with mul.rn.f32x2.
// ---------------------------------------------------------------------------
#define K2_WTG   0
#define K2_BG    30000
#define K2_SMEM_FLOATS 30104

__global__ void __launch_bounds__(THREADS, 1)
k2_gate(const float* __restrict__ sub_emb,
        const float* __restrict__ W_gate,
        const float* __restrict__ b_gate,
        float* __restrict__ out)
{
    extern __shared__ float smem[];
    const int tid = threadIdx.x;

    for (int idx = tid; idx < 300 * 100; idx += THREADS) {
        int k = idx / 100, j = idx - k * 100;
        smem[K2_WTG + j * 300 + k] = W_gate[idx];
    }
    for (int idx = tid; idx < 100; idx += THREADS)
        smem[K2_BG + idx] = b_gate[idx];
    __syncthreads();

    const int warp = tid >> 5, lane = tid & 31;
    const unsigned sbase = (unsigned)__cvta_generic_to_shared(smem);

    unsigned wg_addr[4];
    int jcl[4];
#pragma unroll
    for (int t = 0; t < 4; ++t) {
        int j = lane + 32 * t;
        jcl[t] = (j < 100) ? j : 99;
        wg_addr[t] = sbase + (unsigned)(K2_WTG + jcl[t] * 300) * 4u;
    }

    const int gw = blockIdx.x * WARPS + warp;
    const int nw = gridDim.x * WARPS;

    for (int b = gw; b < NB; b += nw) {
        const float* serow = sub_emb  + (size_t)b * 500;
        const float* smrow = g_submem + (size_t)b * 500;

        unsigned long long acc[5][4];
#pragma unroll
        for (int r = 0; r < 5; ++r)
#pragma unroll
            for (int t = 0; t < 4; ++t) acc[r][t] = 0ULL;

        // range 0: x = sub_emb, W cols [0,100)
#pragma unroll 2
        for (int k = 0; k < 100; k += 4) {
            unsigned long long w0[4], w1[4];
#pragma unroll
            for (int t = 0; t < 4; ++t) lds2(w0[t], w1[t], wg_addr[t] + k * 4);
#pragma unroll
            for (int r = 0; r < 5; ++r) {
                unsigned long long a0, a1;
                ldg2(a0, a1, serow + r * 100 + k);
#pragma unroll
                for (int t = 0; t < 4; ++t) {
                    fma2(acc[r][t], a0, w0[t]);
                    fma2(acc[r][t], a1, w1[t]);
                }
            }
        }
        // range 1: x = sub_mem, W cols [100,200)
#pragma unroll 2
        for (int k = 0; k < 100; k += 4) {
            unsigned long long w0[4], w1[4];
#pragma unroll
            for (int t = 0; t < 4; ++t) lds2(w0[t], w1[t], wg_addr[t] + 400 + k * 4);
#pragma unroll
            for (int r = 0; r < 5; ++r) {
                unsigned long long a0, a1;
                ldg2(a0, a1, smrow + r * 100 + k);
#pragma unroll
                for (int t = 0; t < 4; ++t) {
                    fma2(acc[r][t], a0, w0[t]);
                    fma2(acc[r][t], a1, w1[t]);
                }
            }
        }
        // range 2: x = se*sm (computed), W cols [200,300)
#pragma unroll 1
        for (int k = 0; k < 100; k += 4) {
            unsigned long long w0[4], w1[4];
#pragma unroll
            for (int t = 0; t < 4; ++t) lds2(w0[t], w1[t], wg_addr[t] + 800 + k * 4);
#pragma unroll
            for (int r = 0; r < 5; ++r) {
                unsigned long long a0, a1, c0, c1;
                ldg2(a0, a1, serow + r * 100 + k);
                ldg2(c0, c1, smrow + r * 100 + k);
                mul2(a0, a0, c0);
                mul2(a1, a1, c1);
#pragma unroll
                for (int t = 0; t < 4; ++t) {
                    fma2(acc[r][t], a0, w0[t]);
                    fma2(acc[r][t], a1, w1[t]);
                }
            }
        }

#pragma unroll
        for (int q = 0; q < 5; ++q)
#pragma unroll
            for (int t = 0; t < 4; ++t) {
                int j = lane + 32 * t;
                if (j < 100) {
                    float2 p = unpack2(acc[q][t]);
                    float z  = p.x + p.y + smem[K2_BG + j];
                    float g  = sigmoid_fast(z);
                    float se = __ldg(serow + q * 100 + j);
                    float sm = __ldg(smrow + q * 100 + j);
                    out[(size_t)b * 500 + q * 100 + j] = fmaf(g, sm - se, se);
                }
            }
    }
}

// ---------------------------------------------------------------------------
extern "C" void kernel_launch(void* const* d_in, const int* in_sizes, int n_in,
                              void* d_out, int out_size) {
    (void)in_sizes; (void)n_in; (void)out_size;
    const float* sub_emb = (const float*)d_in[0];
    const float* memory  = (const float*)d_in[1];
    const int*   sub_len = (const int*)  d_in[2];
    const float* sub_raw = (const float*)d_in[3];
    const float* W_mem   = (const float*)d_in[4];
    const float* b_mem   = (const float*)d_in[5];
    const float* W_sub   = (const float*)d_in[6];
    const float* b_sub   = (const float*)d_in[7];
    const float* W_gate  = (const float*)d_in[8];
    const float* b_gate  = (const float*)d_in[9];
    float* out = (float*)d_out;

    int sms = 148;
    cudaDeviceGetAttribute(&sms, cudaDevAttrMultiProcessorCount, 0);

    const size_t s1 = (size_t)K1_SMEM_FLOATS * sizeof(float);  // 119.6 KiB
    const size_t s2 = (size_t)K2_SMEM_FLOATS * sizeof(float);  // 117.6 KiB
    cudaFuncSetAttribute(k1_attention, cudaFuncAttributeMaxDynamicSharedMemorySize, (int)s1);
    cudaFuncSetAttribute(k2_gate,      cudaFuncAttributeMaxDynamicSharedMemorySize, (int)s2);

    k1_attention<<<sms, THREADS, s1>>>(sub_emb, memory, sub_len, sub_raw,
                                       W_mem, b_mem, W_sub, b_sub);
    k2_gate<<<sms, THREADS, s2>>>(sub_emb, W_gate, b_gate, out);
}

// round 10
// speedup vs baseline: 1.2017x; 1.2017x over previous
#include <cuda_runtime.h>
#include <cstddef>

#define NB      65536
#define THREADS 512
#define WARPS   16

// Scratch for sub_mem between the two kernels.
__device__ float g_submem[(size_t)NB * 500];

// ---------------------------------------------------------------------------
__device__ __forceinline__ void fma2(unsigned long long& acc,
                                     unsigned long long a,
                                     unsigned long long b) {
    asm volatile("fma.rn.f32x2 %0, %1, %2, %0;" : "+l"(acc) : "l"(a), "l"(b));
}
__device__ __forceinline__ void lds2(unsigned long long& a,
                                     unsigned long long& b,
                                     unsigned addr) {
    asm volatile("ld.shared.v2.u64 {%0, %1}, [%2];"
                 : "=l"(a), "=l"(b) : "r"(addr));
}
__device__ __forceinline__ float2 unpack2(unsigned long long v) {
    float2 r;
    asm("mov.b64 {%0, %1}, %2;" : "=f"(r.x), "=f"(r.y) : "l"(v));
    return r;
}
__device__ __forceinline__ float hadd2(unsigned long long v) {
    float2 p = unpack2(v);
    return p.x + p.y;
}
__device__ __forceinline__ float tanh_fast(float x) {
    float e = __expf(2.0f * x);
    return 1.0f - __fdividef(2.0f, 1.0f + e);
}
__device__ __forceinline__ float sigmoid_fast(float x) {
    return __fdividef(1.0f, 1.0f + __expf(-x));
}

// Stage layout per warp: [bsel][r][104] floats, bsel stride 520, total 1040.
#define STG_WARP 1040

// ---------------------------------------------------------------------------
// Kernel 1. Smem (floats):
//  [0,10000)      W_mem^T [j][100]
//  [10000,30400)  W_sub^T [j][204]
//  [30400,30504)  b_mem   [30504,30608) b_sub
//  [30608,+16*1040) per-warp 2-batch stage
// Total 47,248 fl = 184.6 KiB
// ---------------------------------------------------------------------------
#define K1_WTM 0
#define K1_WTS 10000
#define K1_BM  30400
#define K1_BS  30504
#define K1_STG 30608
#define K1_SMEM_FLOATS (K1_STG + WARPS * STG_WARP)

__global__ void __launch_bounds__(THREADS, 1)
k1_attention(const float* __restrict__ sub_emb,
             const float* __restrict__ memory,
             const int*   __restrict__ sub_len,
             const float* __restrict__ sub_raw,
             const float* __restrict__ W_mem,
             const float* __restrict__ b_mem,
             const float* __restrict__ W_sub,
             const float* __restrict__ b_sub)
{
    extern __shared__ float smem[];
    const int tid = threadIdx.x;

    for (int idx = tid; idx < 100 * 100; idx += THREADS) {
        int k = idx / 100, j = idx - k * 100;
        smem[K1_WTM + j * 100 + k] = W_mem[idx];
    }
    for (int idx = tid; idx < 200 * 100; idx += THREADS) {
        int k = idx / 100, j = idx - k * 100;
        smem[K1_WTS + j * 204 + k] = W_sub[idx];
    }
    for (int idx = tid; idx < 100; idx += THREADS) {
        smem[K1_BM + idx] = b_mem[idx];
        smem[K1_BS + idx] = b_sub[idx];
    }
    __syncthreads();

    const int warp = tid >> 5, lane = tid & 31;
    const unsigned sbase = (unsigned)__cvta_generic_to_shared(smem);
    float* stf = smem + K1_STG + warp * STG_WARP;
    const unsigned stq0 = sbase + (unsigned)(K1_STG + warp * STG_WARP) * 4u;
    const unsigned stq1 = stq0 + 520u * 4u;
    const bool q4 = (lane & 4) != 0;          // tail tile: batch1 lanes
    const int  l3 = lane & 3;

    unsigned wma[3], wsa[3];
#pragma unroll
    for (int t = 0; t < 3; ++t) {
        int j = lane + 32 * t;                 // j in [0,96)
        wma[t] = sbase + (unsigned)(K1_WTM + j * 100) * 4u;
        wsa[t] = sbase + (unsigned)(K1_WTS + j * 204) * 4u;
    }
    const int j3 = 96 + l3;
    const unsigned wma3 = sbase + (unsigned)(K1_WTM + j3 * 100) * 4u;
    const unsigned wsa3 = sbase + (unsigned)(K1_WTS + j3 * 204) * 4u;

    unsigned long long A0[5][3], A1[5][3], A3[5];

    auto zero_acc = [&]() {
#pragma unroll
        for (int r = 0; r < 5; ++r) {
#pragma unroll
            for (int t = 0; t < 3; ++t) { A0[r][t] = 0ULL; A1[r][t] = 0ULL; }
            A3[r] = 0ULL;
        }
    };
    // fill both batches' 5x100 rows into the stage
    auto fill2 = [&](const float* row0, const float* row1) {
        __syncwarp();
#pragma unroll
        for (int it = 0; it < 8; ++it) {
            int i = lane + 32 * it;
            if (i < 250) {
                int bs = (i >= 125) ? 1 : 0;
                int e  = (i - 125 * bs) * 4;
                int r  = e / 100, k = e - r * 100;
                float4 v = *(const float4*)((bs ? row1 : row0) + e);
                *(float4*)(stf + bs * 520 + r * 104 + k) = v;
            }
        }
        __syncwarp();
    };
    // K=100 GEMV accumulate; c0 = weight column byte offset
    auto gemv = [&](const unsigned* wt, unsigned wt3, int c0) {
#pragma unroll 1
        for (int k = 0; k < 100; k += 4) {
            unsigned long long w0a, w0b, w1a, w1b, w2a, w2b, w3a, w3b;
            lds2(w0a, w0b, wt[0] + c0 + k * 4);
            lds2(w1a, w1b, wt[1] + c0 + k * 4);
            lds2(w2a, w2b, wt[2] + c0 + k * 4);
            lds2(w3a, w3b, wt3   + c0 + k * 4);
#pragma unroll
            for (int r = 0; r < 5; ++r) {
                unsigned long long x0a, x0b, x1a, x1b;
                lds2(x0a, x0b, stq0 + (r * 104 + k) * 4);
                lds2(x1a, x1b, stq1 + (r * 104 + k) * 4);
                fma2(A0[r][0], x0a, w0a); fma2(A0[r][0], x0b, w0b);
                fma2(A0[r][1], x0a, w1a); fma2(A0[r][1], x0b, w1b);
                fma2(A0[r][2], x0a, w2a); fma2(A0[r][2], x0b, w2b);
                fma2(A1[r][0], x1a, w0a); fma2(A1[r][0], x1b, w0b);
                fma2(A1[r][1], x1a, w1a); fma2(A1[r][1], x1b, w1b);
                fma2(A1[r][2], x1a, w2a); fma2(A1[r][2], x1b, w2b);
                unsigned long long xsa = q4 ? x1a : x0a;
                unsigned long long xsb = q4 ? x1b : x0b;
                fma2(A3[r], xsa, w3a); fma2(A3[r], xsb, w3b);
            }
        }
    };

    const int gw = blockIdx.x * WARPS + warp;
    const int nw = gridDim.x * WARPS;

    for (int p = gw; p < NB / 2; p += nw) {
        const int b0 = 2 * p, b1 = 2 * p + 1;
        const float* m0 = memory  + (size_t)b0 * 500;
        const float* m1 = memory  + (size_t)b1 * 500;
        const float* s0 = sub_emb + (size_t)b0 * 500;
        const float* s1 = sub_emb + (size_t)b1 * 500;
        const float* r0 = sub_raw + (size_t)b0 * 500;
        const float* r1 = sub_raw + (size_t)b1 * 500;

        // ---- sub_4att: cat(sub_emb, raw) @ W_sub ----
        zero_acc();
        fill2(s0, s1); gemv(wsa, wsa3, 0);
        fill2(r0, r1); gemv(wsa, wsa3, 400);
        float vsA[5][3], vsB[5][3], vs3[5];
#pragma unroll
        for (int r = 0; r < 5; ++r) {
#pragma unroll
            for (int t = 0; t < 3; ++t) {
                float bb = smem[K1_BS + lane + 32 * t];
                vsA[r][t] = tanh_fast(hadd2(A0[r][t]) + bb);
                vsB[r][t] = tanh_fast(hadd2(A1[r][t]) + bb);
            }
            vs3[r] = tanh_fast(hadd2(A3[r]) + smem[K1_BS + j3]);
        }

        // ---- mem_4att: memory @ W_mem (stage keeps memory for epilogue) ----
        zero_acc();
        fill2(m0, m1); gemv(wma, wma3, 0);
        float vmA[5][3], vmB[5][3], vm3[5];
#pragma unroll
        for (int r = 0; r < 5; ++r) {
#pragma unroll
            for (int t = 0; t < 3; ++t) {
                float bb = smem[K1_BM + lane + 32 * t];
                vmA[r][t] = tanh_fast(hadd2(A0[r][t]) + bb);
                vmB[r][t] = tanh_fast(hadd2(A1[r][t]) + bb);
            }
            vm3[r] = tanh_fast(hadd2(A3[r]) + smem[K1_BM + j3]);
        }

        // ---- per-batch attention + softmax + sub_mem ----
#pragma unroll
        for (int X = 0; X < 2; ++X) {
            const int   bb   = X ? b1 : b0;
            const bool  mine3 = ((lane >> 2) == X);

            float att[5][5];
#pragma unroll
            for (int q = 0; q < 5; ++q)
#pragma unroll
                for (int kk = 0; kk < 5; ++kk) {
                    float pv;
                    if (X == 0) {
                        pv = vsA[q][0] * vmA[kk][0];
                        pv = fmaf(vsA[q][1], vmA[kk][1], pv);
                        pv = fmaf(vsA[q][2], vmA[kk][2], pv);
                    } else {
                        pv = vsB[q][0] * vmB[kk][0];
                        pv = fmaf(vsB[q][1], vmB[kk][1], pv);
                        pv = fmaf(vsB[q][2], vmB[kk][2], pv);
                    }
                    if (mine3) pv = fmaf(vs3[q], vm3[kk], pv);
                    pv += __shfl_xor_sync(0xffffffffu, pv, 16);
                    pv += __shfl_xor_sync(0xffffffffu, pv, 8);
                    pv += __shfl_xor_sync(0xffffffffu, pv, 4);
                    pv += __shfl_xor_sync(0xffffffffu, pv, 2);
                    pv += __shfl_xor_sync(0xffffffffu, pv, 1);
                    att[q][kk] = pv;
                }

            const int slen = __ldg(sub_len + bb);
            float wgt[5][5];
#pragma unroll
            for (int q = 0; q < 5; ++q) {
                if (q < slen) {
                    float m = att[q][0];
#pragma unroll
                    for (int kk = 1; kk < 5; ++kk) m = fmaxf(m, att[q][kk]);
                    float e[5], s = 0.f;
#pragma unroll
                    for (int kk = 0; kk < 5; ++kk) { e[kk] = __expf(att[q][kk] - m); s += e[kk]; }
                    float inv = __fdividef(1.f, s);
#pragma unroll
                    for (int kk = 0; kk < 5; ++kk) wgt[q][kk] = e[kk] * inv;
                } else {
#pragma unroll
                    for (int kk = 0; kk < 5; ++kk) wgt[q][kk] = 0.f;
                }
            }

            // sub_mem from the staged memory rows
            const float* stx = stf + X * 520;
            float mv[5][3], mvt[5];
#pragma unroll
            for (int kk = 0; kk < 5; ++kk) {
#pragma unroll
                for (int t = 0; t < 3; ++t)
                    mv[kk][t] = stx[kk * 104 + lane + 32 * t];
                mvt[kk] = stx[kk * 104 + 96 + l3];
            }
            float* orow = g_submem + (size_t)bb * 500;
#pragma unroll
            for (int q = 0; q < 5; ++q) {
                float a0 = 0.f, a1 = 0.f, a2 = 0.f, a3v = 0.f;
#pragma unroll
                for (int kk = 0; kk < 5; ++kk) {
                    a0  = fmaf(wgt[q][kk], mv[kk][0], a0);
                    a1  = fmaf(wgt[q][kk], mv[kk][1], a1);
                    a2  = fmaf(wgt[q][kk], mv[kk][2], a2);
                    a3v = fmaf(wgt[q][kk], mvt[kk], a3v);
                }
                orow[q * 100 + lane]      = a0;
                orow[q * 100 + lane + 32] = a1;
                orow[q * 100 + lane + 64] = a2;
                if (mine3) orow[q * 100 + 96 + l3] = a3v;
            }
        }
    }
}

// ---------------------------------------------------------------------------
// Kernel 2. Smem (floats):
//  [0,30000)      W_gate^T [j][300]
//  [30000,30104)  b_gate
//  [30104,+16*1040) per-warp 2-batch stage
// Total 46,744 fl = 182.6 KiB
// ---------------------------------------------------------------------------
#define K2_WTG 0
#define K2_BG  30000
#define K2_STG 30104
#define K2_SMEM_FLOATS (K2_STG + WARPS * STG_WARP)

__global__ void __launch_bounds__(THREADS, 1)
k2_gate(const float* __restrict__ sub_emb,
        const float* __restrict__ W_gate,
        const float* __restrict__ b_gate,
        float* __restrict__ out)
{
    extern __shared__ float smem[];
    const int tid = threadIdx.x;

    for (int idx = tid; idx < 300 * 100; idx += THREADS) {
        int k = idx / 100, j = idx - k * 100;
        smem[K2_WTG + j * 300 + k] = W_gate[idx];
    }
    for (int idx = tid; idx < 100; idx += THREADS)
        smem[K2_BG + idx] = b_gate[idx];
    __syncthreads();

    const int warp = tid >> 5, lane = tid & 31;
    const unsigned sbase = (unsigned)__cvta_generic_to_shared(smem);
    float* stf = smem + K2_STG + warp * STG_WARP;
    const unsigned stq0 = sbase + (unsigned)(K2_STG + warp * STG_WARP) * 4u;
    const unsigned stq1 = stq0 + 520u * 4u;
    const bool q4 = (lane & 4) != 0;
    const int  l3 = lane & 3;

    unsigned wga[3];
#pragma unroll
    for (int t = 0; t < 3; ++t)
        wga[t] = sbase + (unsigned)(K2_WTG + (lane + 32 * t) * 300) * 4u;
    const int j3 = 96 + l3;
    const unsigned wga3 = sbase + (unsigned)(K2_WTG + j3 * 300) * 4u;

    unsigned long long A0[5][3], A1[5][3], A3[5];

    auto fill2 = [&](const float* row0, const float* row1) {
        __syncwarp();
#pragma unroll
        for (int it = 0; it < 8; ++it) {
            int i = lane + 32 * it;
            if (i < 250) {
                int bs = (i >= 125) ? 1 : 0;
                int e  = (i - 125 * bs) * 4;
                int r  = e / 100, k = e - r * 100;
                float4 v = *(const float4*)((bs ? row1 : row0) + e);
                *(float4*)(stf + bs * 520 + r * 104 + k) = v;
            }
        }
        __syncwarp();
    };
    auto fill2_prod = [&](const float* sa0, const float* sa1,
                          const float* sb0, const float* sb1) {
        __syncwarp();
#pragma unroll
        for (int it = 0; it < 8; ++it) {
            int i = lane + 32 * it;
            if (i < 250) {
                int bs = (i >= 125) ? 1 : 0;
                int e  = (i - 125 * bs) * 4;
                int r  = e / 100, k = e - r * 100;
                float4 a = *(const float4*)((bs ? sa1 : sa0) + e);
                float4 c = *(const float4*)((bs ? sb1 : sb0) + e);
                float4 v = make_float4(a.x * c.x, a.y * c.y, a.z * c.z, a.w * c.w);
                *(float4*)(stf + bs * 520 + r * 104 + k) = v;
            }
        }
        __syncwarp();
    };
    auto gemv = [&](int c0) {
#pragma unroll 1
        for (int k = 0; k < 100; k += 4) {
            unsigned long long w0a, w0b, w1a, w1b, w2a, w2b, w3a, w3b;
            lds2(w0a, w0b, wga[0] + c0 + k * 4);
            lds2(w1a, w1b, wga[1] + c0 + k * 4);
            lds2(w2a, w2b, wga[2] + c0 + k * 4);
            lds2(w3a, w3b, wga3   + c0 + k * 4);
#pragma unroll
            for (int r = 0; r < 5; ++r) {
                unsigned long long x0a, x0b, x1a, x1b;
                lds2(x0a, x0b, stq0 + (r * 104 + k) * 4);
                lds2(x1a, x1b, stq1 + (r * 104 + k) * 4);
                fma2(A0[r][0], x0a, w0a); fma2(A0[r][0], x0b, w0b);
                fma2(A0[r][1], x0a, w1a); fma2(A0[r][1], x0b, w1b);
                fma2(A0[r][2], x0a, w2a); fma2(A0[r][2], x0b, w2b);
                fma2(A1[r][0], x1a, w0a); fma2(A1[r][0], x1b, w0b);
                fma2(A1[r][1], x1a, w1a); fma2(A1[r][1], x1b, w1b);
                fma2(A1[r][2], x1a, w2a); fma2(A1[r][2], x1b, w2b);
                unsigned long long xsa = q4 ? x1a : x0a;
                unsigned long long xsb = q4 ? x1b : x0b;
                fma2(A3[r], xsa, w3a); fma2(A3[r], xsb, w3b);
            }
        }
    };

    const int gw = blockIdx.x * WARPS + warp;
    const int nw = gridDim.x * WARPS;

    for (int p = gw; p < NB / 2; p += nw) {
        const int b0 = 2 * p, b1 = 2 * p + 1;
        const float* se0 = sub_emb  + (size_t)b0 * 500;
        const float* se1 = sub_emb  + (size_t)b1 * 500;
        const float* sm0 = g_submem + (size_t)b0 * 500;
        const float* sm1 = g_submem + (size_t)b1 * 500;

#pragma unroll
        for (int r = 0; r < 5; ++r) {
#pragma unroll
            for (int t = 0; t < 3; ++t) { A0[r][t] = 0ULL; A1[r][t] = 0ULL; }
            A3[r] = 0ULL;
        }

        fill2(se0, se1);                 gemv(0);
        fill2(sm0, sm1);                 gemv(400);
        fill2_prod(se0, se1, sm0, sm1);  gemv(800);

#pragma unroll
        for (int X = 0; X < 2; ++X) {
            const int bb = X ? b1 : b0;
            const float* se = X ? se1 : se0;
            const float* sm = X ? sm1 : sm0;
            float* orow = out + (size_t)bb * 500;
#pragma unroll
            for (int q = 0; q < 5; ++q) {
#pragma unroll
                for (int t = 0; t < 3; ++t) {
                    int j = lane + 32 * t;
                    float z = (X ? hadd2(A1[q][t]) : hadd2(A0[q][t]))
                              + smem[K2_BG + j];
                    float g  = sigmoid_fast(z);
                    float a  = __ldg(se + q * 100 + j);
                    float c  = __ldg(sm + q * 100 + j);
                    orow[q * 100 + j] = fmaf(g, c - a, a);
                }
                if ((lane >> 2) == X) {
                    float z = hadd2(A3[q]) + smem[K2_BG + j3];
                    float g  = sigmoid_fast(z);
                    float a  = __ldg(se + q * 100 + j3);
                    float c  = __ldg(sm + q * 100 + j3);
                    orow[q * 100 + j3] = fmaf(g, c - a, a);
                }
            }
        }
    }
}

// ---------------------------------------------------------------------------
extern "C" void kernel_launch(void* const* d_in, const int* in_sizes, int n_in,
                              void* d_out, int out_size) {
    (void)in_sizes; (void)n_in; (void)out_size;
    const float* sub_emb = (const float*)d_in[0];
    const float* memory  = (const float*)d_in[1];
    const int*   sub_len = (const int*)  d_in[2];
    const float* sub_raw = (const float*)d_in[3];
    const float* W_mem   = (const float*)d_in[4];
    const float* b_mem   = (const float*)d_in[5];
    const float* W_sub   = (const float*)d_in[6];
    const float* b_sub   = (const float*)d_in[7];
    const float* W_gate  = (const float*)d_in[8];
    const float* b_gate  = (const float*)d_in[9];
    float* out = (float*)d_out;

    int sms = 148;
    cudaDeviceGetAttribute(&sms, cudaDevAttrMultiProcessorCount, 0);

    const size_t s1 = (size_t)K1_SMEM_FLOATS * sizeof(float);  // 184.6 KiB
    const size_t s2 = (size_t)K2_SMEM_FLOATS * sizeof(float);  // 182.6 KiB
    cudaFuncSetAttribute(k1_attention, cudaFuncAttributeMaxDynamicSharedMemorySize, (int)s1);
    cudaFuncSetAttribute(k2_gate,      cudaFuncAttributeMaxDynamicSharedMemorySize, (int)s2);

    k1_attention<<<sms, THREADS, s1>>>(sub_emb, memory, sub_len, sub_raw,
                                       W_mem, b_mem, W_sub, b_sub);
    k2_gate<<<sms, THREADS, s2>>>(sub_emb, W_gate, b_gate, out);
}

// round 11
// speedup vs baseline: 1.2031x; 1.0011x over previous
#include <cuda_runtime.h>
#include <cstddef>

#define NB      65536
#define THREADS 512
#define WARPS   16

// Scratch for sub_mem between the two kernels.
__device__ float g_submem[(size_t)NB * 500];

// ---------------------------------------------------------------------------
__device__ __forceinline__ void fma2(unsigned long long& acc,
                                     unsigned long long a,
                                     unsigned long long b) {
    asm volatile("fma.rn.f32x2 %0, %1, %2, %0;" : "+l"(acc) : "l"(a), "l"(b));
}
__device__ __forceinline__ void lds2(unsigned long long& a,
                                     unsigned long long& b,
                                     unsigned addr) {
    asm volatile("ld.shared.v2.u64 {%0, %1}, [%2];"
                 : "=l"(a), "=l"(b) : "r"(addr));
}
__device__ __forceinline__ float2 unpack2(unsigned long long v) {
    float2 r;
    asm("mov.b64 {%0, %1}, %2;" : "=f"(r.x), "=f"(r.y) : "l"(v));
    return r;
}
__device__ __forceinline__ float hadd2(unsigned long long v) {
    float2 p = unpack2(v);
    return p.x + p.y;
}
__device__ __forceinline__ float tanh_fast(float x) {
    float e = __expf(2.0f * x);
    return 1.0f - __fdividef(2.0f, 1.0f + e);
}
__device__ __forceinline__ float sigmoid_fast(float x) {
    return __fdividef(1.0f, 1.0f + __expf(-x));
}

// Stage layout per warp: [bsel][r][104] floats, bsel stride 520, total 1040.
#define STG_WARP 1040

// ---------------------------------------------------------------------------
// Kernel 1. Smem (floats):
//  [0,10000)      W_mem^T [j][100]
//  [10000,30400)  W_sub^T [j][204]
//  [30400,30504)  b_mem   [30504,30608) b_sub
//  [30608,+16*1040) per-warp 2-batch stage
// Total 47,248 fl = 184.6 KiB
// ---------------------------------------------------------------------------
#define K1_WTM 0
#define K1_WTS 10000
#define K1_BM  30400
#define K1_BS  30504
#define K1_STG 30608
#define K1_SMEM_FLOATS (K1_STG + WARPS * STG_WARP)

__global__ void __launch_bounds__(THREADS, 1)
k1_attention(const float* __restrict__ sub_emb,
             const float* __restrict__ memory,
             const int*   __restrict__ sub_len,
             const float* __restrict__ sub_raw,
             const float* __restrict__ W_mem,
             const float* __restrict__ b_mem,
             const float* __restrict__ W_sub,
             const float* __restrict__ b_sub)
{
    extern __shared__ float smem[];
    const int tid = threadIdx.x;

    for (int idx = tid; idx < 100 * 100; idx += THREADS) {
        int k = idx / 100, j = idx - k * 100;
        smem[K1_WTM + j * 100 + k] = W_mem[idx];
    }
    for (int idx = tid; idx < 200 * 100; idx += THREADS) {
        int k = idx / 100, j = idx - k * 100;
        smem[K1_WTS + j * 204 + k] = W_sub[idx];
    }
    for (int idx = tid; idx < 100; idx += THREADS) {
        smem[K1_BM + idx] = b_mem[idx];
        smem[K1_BS + idx] = b_sub[idx];
    }
    __syncthreads();

    const int warp = tid >> 5, lane = tid & 31;
    const unsigned sbase = (unsigned)__cvta_generic_to_shared(smem);
    float* stf = smem + K1_STG + warp * STG_WARP;
    const unsigned stq0 = sbase + (unsigned)(K1_STG + warp * STG_WARP) * 4u;
    const unsigned stq1 = stq0 + 520u * 4u;
    const bool q4 = (lane & 4) != 0;          // tail tile: batch1 lanes
    const int  l3 = lane & 3;

    unsigned wma[3], wsa[3];
#pragma unroll
    for (int t = 0; t < 3; ++t) {
        int j = lane + 32 * t;                 // j in [0,96)
        wma[t] = sbase + (unsigned)(K1_WTM + j * 100) * 4u;
        wsa[t] = sbase + (unsigned)(K1_WTS + j * 204) * 4u;
    }
    const int j3 = 96 + l3;
    const unsigned wma3 = sbase + (unsigned)(K1_WTM + j3 * 100) * 4u;
    const unsigned wsa3 = sbase + (unsigned)(K1_WTS + j3 * 204) * 4u;

    unsigned long long A0[5][3], A1[5][3], A3[5];

    auto zero_acc = [&]() {
#pragma unroll
        for (int r = 0; r < 5; ++r) {
#pragma unroll
            for (int t = 0; t < 3; ++t) { A0[r][t] = 0ULL; A1[r][t] = 0ULL; }
            A3[r] = 0ULL;
        }
    };
    // fill both batches' 5x100 rows into the stage
    auto fill2 = [&](const float* row0, const float* row1) {
        __syncwarp();
#pragma unroll
        for (int it = 0; it < 8; ++it) {
            int i = lane + 32 * it;
            if (i < 250) {
                int bs = (i >= 125) ? 1 : 0;
                int e  = (i - 125 * bs) * 4;
                int r  = e / 100, k = e - r * 100;
                float4 v = *(const float4*)((bs ? row1 : row0) + e);
                *(float4*)(stf + bs * 520 + r * 104 + k) = v;
            }
        }
        __syncwarp();
    };
    // K=100 GEMV accumulate; c0 = weight column byte offset
    auto gemv = [&](const unsigned* wt, unsigned wt3, int c0) {
#pragma unroll 1
        for (int k = 0; k < 100; k += 4) {
            unsigned long long w0a, w0b, w1a, w1b, w2a, w2b, w3a, w3b;
            lds2(w0a, w0b, wt[0] + c0 + k * 4);
            lds2(w1a, w1b, wt[1] + c0 + k * 4);
            lds2(w2a, w2b, wt[2] + c0 + k * 4);
            lds2(w3a, w3b, wt3   + c0 + k * 4);
#pragma unroll
            for (int r = 0; r < 5; ++r) {
                unsigned long long x0a, x0b, x1a, x1b;
                lds2(x0a, x0b, stq0 + (r * 104 + k) * 4);
                lds2(x1a, x1b, stq1 + (r * 104 + k) * 4);
                fma2(A0[r][0], x0a, w0a); fma2(A0[r][0], x0b, w0b);
                fma2(A0[r][1], x0a, w1a); fma2(A0[r][1], x0b, w1b);
                fma2(A0[r][2], x0a, w2a); fma2(A0[r][2], x0b, w2b);
                fma2(A1[r][0], x1a, w0a); fma2(A1[r][0], x1b, w0b);
                fma2(A1[r][1], x1a, w1a); fma2(A1[r][1], x1b, w1b);
                fma2(A1[r][2], x1a, w2a); fma2(A1[r][2], x1b, w2b);
                unsigned long long xsa = q4 ? x1a : x0a;
                unsigned long long xsb = q4 ? x1b : x0b;
                fma2(A3[r], xsa, w3a); fma2(A3[r], xsb, w3b);
            }
        }
    };

    const int gw = blockIdx.x * WARPS + warp;
    const int nw = gridDim.x * WARPS;

    for (int p = gw; p < NB / 2; p += nw) {
        const int b0 = 2 * p, b1 = 2 * p + 1;
        const float* m0 = memory  + (size_t)b0 * 500;
        const float* m1 = memory  + (size_t)b1 * 500;
        const float* s0 = sub_emb + (size_t)b0 * 500;
        const float* s1 = sub_emb + (size_t)b1 * 500;
        const float* r0 = sub_raw + (size_t)b0 * 500;
        const float* r1 = sub_raw + (size_t)b1 * 500;

        // ---- sub_4att: cat(sub_emb, raw) @ W_sub ----
        zero_acc();
        fill2(s0, s1); gemv(wsa, wsa3, 0);
        fill2(r0, r1); gemv(wsa, wsa3, 400);
        float vsA[5][3], vsB[5][3], vs3[5];
#pragma unroll
        for (int r = 0; r < 5; ++r) {
#pragma unroll
            for (int t = 0; t < 3; ++t) {
                float bb = smem[K1_BS + lane + 32 * t];
                vsA[r][t] = tanh_fast(hadd2(A0[r][t]) + bb);
                vsB[r][t] = tanh_fast(hadd2(A1[r][t]) + bb);
            }
            vs3[r] = tanh_fast(hadd2(A3[r]) + smem[K1_BS + j3]);
        }

        // ---- mem_4att: memory @ W_mem (stage keeps memory for epilogue) ----
        zero_acc();
        fill2(m0, m1); gemv(wma, wma3, 0);
        float vmA[5][3], vmB[5][3], vm3[5];
#pragma unroll
        for (int r = 0; r < 5; ++r) {
#pragma unroll
            for (int t = 0; t < 3; ++t) {
                float bb = smem[K1_BM + lane + 32 * t];
                vmA[r][t] = tanh_fast(hadd2(A0[r][t]) + bb);
                vmB[r][t] = tanh_fast(hadd2(A1[r][t]) + bb);
            }
            vm3[r] = tanh_fast(hadd2(A3[r]) + smem[K1_BM + j3]);
        }

        // ---- per-batch attention + softmax + sub_mem ----
#pragma unroll
        for (int X = 0; X < 2; ++X) {
            const int   bb   = X ? b1 : b0;
            const bool  mine3 = ((lane >> 2) == X);

            float att[5][5];
#pragma unroll
            for (int q = 0; q < 5; ++q)
#pragma unroll
                for (int kk = 0; kk < 5; ++kk) {
                    float pv;
                    if (X == 0) {
                        pv = vsA[q][0] * vmA[kk][0];
                        pv = fmaf(vsA[q][1], vmA[kk][1], pv);
                        pv = fmaf(vsA[q][2], vmA[kk][2], pv);
                    } else {
                        pv = vsB[q][0] * vmB[kk][0];
                        pv = fmaf(vsB[q][1], vmB[kk][1], pv);
                        pv = fmaf(vsB[q][2], vmB[kk][2], pv);
                    }
                    if (mine3) pv = fmaf(vs3[q], vm3[kk], pv);
                    pv += __shfl_xor_sync(0xffffffffu, pv, 16);
                    pv += __shfl_xor_sync(0xffffffffu, pv, 8);
                    pv += __shfl_xor_sync(0xffffffffu, pv, 4);
                    pv += __shfl_xor_sync(0xffffffffu, pv, 2);
                    pv += __shfl_xor_sync(0xffffffffu, pv, 1);
                    att[q][kk] = pv;
                }

            const int slen = __ldg(sub_len + bb);
            float wgt[5][5];
#pragma unroll
            for (int q = 0; q < 5; ++q) {
                if (q < slen) {
                    float m = att[q][0];
#pragma unroll
                    for (int kk = 1; kk < 5; ++kk) m = fmaxf(m, att[q][kk]);
                    float e[5], s = 0.f;
#pragma unroll
                    for (int kk = 0; kk < 5; ++kk) { e[kk] = __expf(att[q][kk] - m); s += e[kk]; }
                    float inv = __fdividef(1.f, s);
#pragma unroll
                    for (int kk = 0; kk < 5; ++kk) wgt[q][kk] = e[kk] * inv;
                } else {
#pragma unroll
                    for (int kk = 0; kk < 5; ++kk) wgt[q][kk] = 0.f;
                }
            }

            // sub_mem from the staged memory rows
            const float* stx = stf + X * 520;
            float mv[5][3], mvt[5];
#pragma unroll
            for (int kk = 0; kk < 5; ++kk) {
#pragma unroll
                for (int t = 0; t < 3; ++t)
                    mv[kk][t] = stx[kk * 104 + lane + 32 * t];
                mvt[kk] = stx[kk * 104 + 96 + l3];
            }
            float* orow = g_submem + (size_t)bb * 500;
#pragma unroll
            for (int q = 0; q < 5; ++q) {
                float a0 = 0.f, a1 = 0.f, a2 = 0.f, a3v = 0.f;
#pragma unroll
                for (int kk = 0; kk < 5; ++kk) {
                    a0  = fmaf(wgt[q][kk], mv[kk][0], a0);
                    a1  = fmaf(wgt[q][kk], mv[kk][1], a1);
                    a2  = fmaf(wgt[q][kk], mv[kk][2], a2);
                    a3v = fmaf(wgt[q][kk], mvt[kk], a3v);
                }
                orow[q * 100 + lane]      = a0;
                orow[q * 100 + lane + 32] = a1;
                orow[q * 100 + lane + 64] = a2;
                if (mine3) orow[q * 100 + 96 + l3] = a3v;
            }
        }
    }
}

// ---------------------------------------------------------------------------
// Kernel 2. Smem (floats):
//  [0,30000)      W_gate^T [j][300]
//  [30000,30104)  b_gate
//  [30104,+16*1040) per-warp 2-batch stage
// Total 46,744 fl = 182.6 KiB
// ---------------------------------------------------------------------------
#define K2_WTG 0
#define K2_BG  30000
#define K2_STG 30104
#define K2_SMEM_FLOATS (K2_STG + WARPS * STG_WARP)

__global__ void __launch_bounds__(THREADS, 1)
k2_gate(const float* __restrict__ sub_emb,
        const float* __restrict__ W_gate,
        const float* __restrict__ b_gate,
        float* __restrict__ out)
{
    extern __shared__ float smem[];
    const int tid = threadIdx.x;

    for (int idx = tid; idx < 300 * 100; idx += THREADS) {
        int k = idx / 100, j = idx - k * 100;
        smem[K2_WTG + j * 300 + k] = W_gate[idx];
    }
    for (int idx = tid; idx < 100; idx += THREADS)
        smem[K2_BG + idx] = b_gate[idx];
    __syncthreads();

    const int warp = tid >> 5, lane = tid & 31;
    const unsigned sbase = (unsigned)__cvta_generic_to_shared(smem);
    float* stf = smem + K2_STG + warp * STG_WARP;
    const unsigned stq0 = sbase + (unsigned)(K2_STG + warp * STG_WARP) * 4u;
    const unsigned stq1 = stq0 + 520u * 4u;
    const bool q4 = (lane & 4) != 0;
    const int  l3 = lane & 3;

    unsigned wga[3];
#pragma unroll
    for (int t = 0; t < 3; ++t)
        wga[t] = sbase + (unsigned)(K2_WTG + (lane + 32 * t) * 300) * 4u;
    const int j3 = 96 + l3;
    const unsigned wga3 = sbase + (unsigned)(K2_WTG + j3 * 300) * 4u;

    unsigned long long A0[5][3], A1[5][3], A3[5];

    auto fill2 = [&](const float* row0, const float* row1) {
        __syncwarp();
#pragma unroll
        for (int it = 0; it < 8; ++it) {
            int i = lane + 32 * it;
            if (i < 250) {
                int bs = (i >= 125) ? 1 : 0;
                int e  = (i - 125 * bs) * 4;
                int r  = e / 100, k = e - r * 100;
                float4 v = *(const float4*)((bs ? row1 : row0) + e);
                *(float4*)(stf + bs * 520 + r * 104 + k) = v;
            }
        }
        __syncwarp();
    };
    auto fill2_prod = [&](const float* sa0, const float* sa1,
                          const float* sb0, const float* sb1) {
        __syncwarp();
#pragma unroll
        for (int it = 0; it < 8; ++it) {
            int i = lane + 32 * it;
            if (i < 250) {
                int bs = (i >= 125) ? 1 : 0;
                int e  = (i - 125 * bs) * 4;
                int r  = e / 100, k = e - r * 100;
                float4 a = *(const float4*)((bs ? sa1 : sa0) + e);
                float4 c = *(const float4*)((bs ? sb1 : sb0) + e);
                float4 v = make_float4(a.x * c.x, a.y * c.y, a.z * c.z, a.w * c.w);
                *(float4*)(stf + bs * 520 + r * 104 + k) = v;
            }
        }
        __syncwarp();
    };
    auto gemv = [&](int c0) {
#pragma unroll 1
        for (int k = 0; k < 100; k += 4) {
            unsigned long long w0a, w0b, w1a, w1b, w2a, w2b, w3a, w3b;
            lds2(w0a, w0b, wga[0] + c0 + k * 4);
            lds2(w1a, w1b, wga[1] + c0 + k * 4);
            lds2(w2a, w2b, wga[2] + c0 + k * 4);
            lds2(w3a, w3b, wga3   + c0 + k * 4);
#pragma unroll
            for (int r = 0; r < 5; ++r) {
                unsigned long long x0a, x0b, x1a, x1b;
                lds2(x0a, x0b, stq0 + (r * 104 + k) * 4);
                lds2(x1a, x1b, stq1 + (r * 104 + k) * 4);
                fma2(A0[r][0], x0a, w0a); fma2(A0[r][0], x0b, w0b);
                fma2(A0[r][1], x0a, w1a); fma2(A0[r][1], x0b, w1b);
                fma2(A0[r][2], x0a, w2a); fma2(A0[r][2], x0b, w2b);
                fma2(A1[r][0], x1a, w0a); fma2(A1[r][0], x1b, w0b);
                fma2(A1[r][1], x1a, w1a); fma2(A1[r][1], x1b, w1b);
                fma2(A1[r][2], x1a, w2a); fma2(A1[r][2], x1b, w2b);
                unsigned long long xsa = q4 ? x1a : x0a;
                unsigned long long xsb = q4 ? x1b : x0b;
                fma2(A3[r], xsa, w3a); fma2(A3[r], xsb, w3b);
            }
        }
    };

    const int gw = blockIdx.x * WARPS + warp;
    const int nw = gridDim.x * WARPS;

    for (int p = gw; p < NB / 2; p += nw) {
        const int b0 = 2 * p, b1 = 2 * p + 1;
        const float* se0 = sub_emb  + (size_t)b0 * 500;
        const float* se1 = sub_emb  + (size_t)b1 * 500;
        const float* sm0 = g_submem + (size_t)b0 * 500;
        const float* sm1 = g_submem + (size_t)b1 * 500;

#pragma unroll
        for (int r = 0; r < 5; ++r) {
#pragma unroll
            for (int t = 0; t < 3; ++t) { A0[r][t] = 0ULL; A1[r][t] = 0ULL; }
            A3[r] = 0ULL;
        }

        fill2(se0, se1);                 gemv(0);
        fill2(sm0, sm1);                 gemv(400);
        fill2_prod(se0, se1, sm0, sm1);  gemv(800);

#pragma unroll
        for (int X = 0; X < 2; ++X) {
            const int bb = X ? b1 : b0;
            const float* se = X ? se1 : se0;
            const float* sm = X ? sm1 : sm0;
            float* orow = out + (size_t)bb * 500;
#pragma unroll
            for (int q = 0; q < 5; ++q) {
#pragma unroll
                for (int t = 0; t < 3; ++t) {
                    int j = lane + 32 * t;
                    float z = (X ? hadd2(A1[q][t]) : hadd2(A0[q][t]))
                              + smem[K2_BG + j];
                    float g  = sigmoid_fast(z);
                    float a  = __ldg(se + q * 100 + j);
                    float c  = __ldg(sm + q * 100 + j);
                    orow[q * 100 + j] = fmaf(g, c - a, a);
                }
                if ((lane >> 2) == X) {
                    float z = hadd2(A3[q]) + smem[K2_BG + j3];
                    float g  = sigmoid_fast(z);
                    float a  = __ldg(se + q * 100 + j3);
                    float c  = __ldg(sm + q * 100 + j3);
                    orow[q * 100 + j3] = fmaf(g, c - a, a);
                }
            }
        }
    }
}

// ---------------------------------------------------------------------------
extern "C" void kernel_launch(void* const* d_in, const int* in_sizes, int n_in,
                              void* d_out, int out_size) {
    (void)in_sizes; (void)n_in; (void)out_size;
    const float* sub_emb = (const float*)d_in[0];
    const float* memory  = (const float*)d_in[1];
    const int*   sub_len = (const int*)  d_in[2];
    const float* sub_raw = (const float*)d_in[3];
    const float* W_mem   = (const float*)d_in[4];
    const float* b_mem   = (const float*)d_in[5];
    const float* W_sub   = (const float*)d_in[6];
    const float* b_sub   = (const float*)d_in[7];
    const float* W_gate  = (const float*)d_in[8];
    const float* b_gate  = (const float*)d_in[9];
    float* out = (float*)d_out;

    int sms = 148;
    cudaDeviceGetAttribute(&sms, cudaDevAttrMultiProcessorCount, 0);

    const size_t s1 = (size_t)K1_SMEM_FLOATS * sizeof(float);  // 184.6 KiB
    const size_t s2 = (size_t)K2_SMEM_FLOATS * sizeof(float);  // 182.6 KiB
    cudaFuncSetAttribute(k1_attention, cudaFuncAttributeMaxDynamicSharedMemorySize, (int)s1);
    cudaFuncSetAttribute(k2_gate,      cudaFuncAttributeMaxDynamicSharedMemorySize, (int)s2);

    k1_attention<<<sms, THREADS, s1>>>(sub_emb, memory, sub_len, sub_raw,
                                       W_mem, b_mem, W_sub, b_sub);
    k2_gate<<<sms, THREADS, s2>>>(sub_emb, W_gate, b_gate, out);
}